// round 15
// baseline (speedup 1.0000x reference)
#include <cuda_runtime.h>
#include <cuda_fp16.h>
#include <cstdint>

// out[b,k] = sum_ij in1[b,i]*in2[b,j]*cb[k,ij]
// R14 + 2 batch rows per thread, packed as half2 lanes:
//   P: half2[81][160]  (.x = row t, .y = row t+160) -> one LDS.32 gather and
//   one meta LDC pair serve BOTH rows (wf/row and LDC/row halved).
//   O: half2[27][161]  (stride 161 words -> R2-proven conflict-free transpose).
// Meta on the constant port (immediate addresses), fixed 4 nnz/k unrolled,
// overflow list for >4-nnz rows. fp16 P + fp16 O -> rel_err ~3e-4 < 1e-3.

#define NK     81
#define NIJ    81
#define TPB    160
#define ROWS   320       // 2 rows per thread
#define OSTR   161       // O stride in half2 units
#define CHUNK  27
#define NPH    3

#define P_BYTES  (NIJ * TPB * 4)                 // half2: 51,840
#define O_BYTES  (CHUNK * OSTR * 4)              // half2: 17,388
#define SMEM_TOT (P_BYTES + O_BYTES)             // 69,228 -> 3 CTAs/SM

struct Tbl {
    float4 meta[NK][2];   // per k: {P_byteoff0,w0,off1,w1} x2 = 4 nnz (off = ij*640)
    int    ovp[NPH + 1];  // overflow rowptr per phase
    int    pad[4];
};

__device__ Tbl    g_stage;
__device__ float4 g_ovf[NK * NIJ];   // {o_bytes(O half2 row), p_bytes, w, 0}
__constant__ Tbl  c_tbl;

__global__ void prep_kernel(const float* __restrict__ cb) {
    __shared__ int ocnt[NK];
    __shared__ int ooff[NK + 1];
    const int k = threadIdx.x;
    if (k < NK) {
        int c = 0;
        for (int ij = 0; ij < NIJ; ij++)
            if (cb[k * NIJ + ij] != 0.f) c++;
        ocnt[k] = (c > 4) ? (c - 4) : 0;
    }
    __syncthreads();
    if (k == 0) {
        int s = 0;
        for (int q = 0; q < NK; q++) { ooff[q] = s; s += ocnt[q]; }
        ooff[NK] = s;
        g_stage.ovp[0] = 0;
        g_stage.ovp[1] = ooff[1 * CHUNK];
        g_stage.ovp[2] = ooff[2 * CHUNK];
        g_stage.ovp[3] = s;              // k-ascending -> phase-contiguous
    }
    __syncthreads();
    if (k < NK) {
        float id[4] = {0.f, 0.f, 0.f, 0.f};
        float w [4] = {0.f, 0.f, 0.f, 0.f};
        int n = 0;
        int o = ooff[k];
        const int kl = k % CHUNK;
        for (int ij = 0; ij < NIJ; ij++) {
            float v = cb[k * NIJ + ij];
            if (v != 0.f) {
                if (n < 4) { id[n] = __int_as_float(ij * TPB * 4); w[n] = v; n++; }
                else g_ovf[o++] = make_float4(__int_as_float(kl * OSTR * 4),
                                              __int_as_float(ij * TPB * 4), v, 0.f);
            }
        }
        g_stage.meta[k][0] = make_float4(id[0], w[0], id[1], w[1]);
        g_stage.meta[k][1] = make_float4(id[2], w[2], id[3], w[3]);
    }
}

__global__ void __launch_bounds__(TPB, 3) tp_kernel(
    const float* __restrict__ in1,
    const float* __restrict__ in2,
    float* __restrict__ out,
    int B)
{
    extern __shared__ char smemc[];
    __half2* P2  = (__half2*)smemc;                 // [81][160]
    __half2* O2  = (__half2*)(smemc + P_BYTES);     // [27][161]
    float*   st1 = (float*)smemc;                   // staging (P region)
    float*   st2 = (float*)(smemc + ROWS * 9 * 4);  // 11,520B offset, 16B-aligned

    const int t = threadIdx.x;
    const int base = blockIdx.x * ROWS;

    // ---- coalesced input staging for 320 rows into the P region ----
    const int avail = B * 9 - base * 9;
    if (avail >= ROWS * 9) {
        const float4* v1 = (const float4*)(in1 + base * 9);  // base*36 % 16 == 0
        const float4* v2 = (const float4*)(in2 + base * 9);
        float4* s1 = (float4*)st1;
        float4* s2 = (float4*)st2;
#pragma unroll
        for (int q = t; q < (ROWS * 9) / 4; q += TPB) { s1[q] = v1[q]; s2[q] = v2[q]; }
    } else {
        for (int q = t; q < ROWS * 9; q += TPB) {
            bool ok = q < avail;
            st1[q] = ok ? in1[base * 9 + q] : 0.f;
            st2[q] = ok ? in2[base * 9 + q] : 0.f;
        }
    }
    __syncthreads();

    float a1[9], c1[9], a2[9], c2[9];
#pragma unroll
    for (int i = 0; i < 9; i++) {
        a1[i] = st1[t * 9 + i];          c1[i] = st2[t * 9 + i];
        a2[i] = st1[(t + TPB) * 9 + i];  c2[i] = st2[(t + TPB) * 9 + i];
    }
    __syncthreads();                     // staging consumed; P region free

    // outer products -> packed half2, own column
    char* Pb = (char*)P2 + t * 4;
#pragma unroll
    for (int i = 0; i < 9; i++)
#pragma unroll
        for (int j = 0; j < 9; j++)
            *(__half2*)(Pb + (i * 9 + j) * (TPB * 4)) =
                __floats2half2_rn(a1[i] * c1[j], a2[i] * c2[j]);

    const int limit  = B * NK;                   // 84,934,656 < 2^31
    const int gbase0 = blockIdx.x * ROWS * NK;
    const int dB     = TPB * NK;                 // +12960 for the second row
    char* Ob = (char*)O2 + t * 4;

#pragma unroll
    for (int ph = 0; ph < NPH; ph++) {
        // ---- contraction: fixed 4 nnz per k, both rows per gather ----
#pragma unroll
        for (int kq = 0; kq < CHUNK; kq++) {
            const float4 m0 = c_tbl.meta[ph * CHUNK + kq][0];
            const float4 m1 = c_tbl.meta[ph * CHUNK + kq][1];
            float2 f0 = __half22float2(*(const __half2*)(Pb + __float_as_int(m0.x)));
            float2 f1 = __half22float2(*(const __half2*)(Pb + __float_as_int(m0.z)));
            float2 f2 = __half22float2(*(const __half2*)(Pb + __float_as_int(m1.x)));
            float2 f3 = __half22float2(*(const __half2*)(Pb + __float_as_int(m1.z)));
            float sA = m0.y * f0.x + m0.w * f1.x;
            float sB = m0.y * f0.y + m0.w * f1.y;
            sA = fmaf(m1.y, f2.x, sA);  sA = fmaf(m1.w, f3.x, sA);
            sB = fmaf(m1.y, f2.y, sB);  sB = fmaf(m1.w, f3.y, sB);
            *(__half2*)(Ob + kq * (OSTR * 4)) = __floats2half2_rn(sA, sB);
        }
        // ---- rare overflow entries (rows with >4 nnz), own-column += ----
        {
            const int r1 = c_tbl.ovp[ph + 1];
#pragma unroll 1
            for (int r = c_tbl.ovp[ph]; r < r1; r++) {
                const float4 e = g_ovf[r];
                float2 pv = __half22float2(*(const __half2*)(Pb + __float_as_int(e.y)));
                __half2* op = (__half2*)(Ob + __float_as_int(e.x));
                float2 cur = __half22float2(*op);
                cur.x = fmaf(e.z, pv.x, cur.x);
                cur.y = fmaf(e.z, pv.y, cur.y);
                *op = __floats2half2_rn(cur.x, cur.y);
            }
        }
        __syncthreads();   // flush reads other threads' O columns

        // ---- coalesced flush: one LDS.32 -> two outputs (rows bl, bl+160) ----
        {
            int bl = t / CHUNK;
            int kq = t - bl * CHUNK;
            int gi = bl * NK + kq;
            int si = kq * OSTR + bl;        // half2 units
            const int gb = gbase0 + ph * CHUNK;
#pragma unroll
            for (int rr = 0; rr < CHUNK; rr++) {
                float2 v = __half22float2(O2[si]);
                int gA = gb + gi;
                int gB = gA + dB;
                if (gA < limit) out[gA] = v.x;
                if (gB < limit) out[gB] = v.y;
                kq += 25;                         // advance slot by TPB=160
                if (kq >= CHUNK) {
                    kq -= CHUNK;
                    gi += 5 * NK + 25 + (NK - CHUNK);        // 484
                    si += 25 * OSTR + 5 - (CHUNK * OSTR - 1);// -316
                } else {
                    gi += 5 * NK + 25;                       // 430
                    si += 25 * OSTR + 5;                     // 4030
                }
            }
        }
        __syncthreads();   // next phase reuses O
    }
}

extern "C" void kernel_launch(void* const* d_in, const int* in_sizes, int n_in,
                              void* d_out, int out_size) {
    const float* in1 = (const float*)d_in[0];
    const float* in2 = (const float*)d_in[1];
    const float* cb  = (const float*)d_in[2];
    float* out = (float*)d_out;

    const int B = in_sizes[0] / 9;
    const int grid = (B + ROWS - 1) / ROWS;

    cudaFuncSetAttribute(tp_kernel,
                         cudaFuncAttributeMaxDynamicSharedMemorySize,
                         SMEM_TOT);      // 69,228 B -> 3 CTAs/SM

    prep_kernel<<<1, 96>>>(cb);

    void *dst = nullptr, *src = nullptr;
    cudaGetSymbolAddress(&dst, c_tbl);
    cudaGetSymbolAddress(&src, g_stage);
    cudaMemcpyAsync(dst, src, sizeof(Tbl), cudaMemcpyDeviceToDevice, 0);

    tp_kernel<<<grid, TPB, SMEM_TOT>>>(in1, in2, out, B);
}